// round 7
// baseline (speedup 1.0000x reference)
#include <cuda_runtime.h>
#include <cuda_fp16.h>
#include <cstdint>

#define VMAX 100000
#define EMAX 1600000

typedef unsigned long long u64;

// ---------------- device scratch (no allocations allowed) ----------------
__device__ int    g_rowptr[VMAX + 1];
__device__ int    g_cnt[VMAX];
__device__ int    g_cols[EMAX];
__device__ float  g_vals[EMAX];
__device__ __half g_xn [(size_t)VMAX * 128];  // BN'ed input (V,32,4) fp16 (layer0 X0)
__device__ float  g_xnf[(size_t)VMAX * 128];  // BN'ed input fp32 (residual path)
__device__ __half g_x0[(size_t)VMAX * 256];
__device__ __half g_x1[(size_t)VMAX * 256];
__device__ __half g_x2[(size_t)VMAX * 256];
__device__ __half g_x3[(size_t)VMAX * 256];
__device__ __half g_t [(size_t)VMAX * 256];   // fp16 einsum out (layers 0,1)
__device__ float  g_of[(size_t)VMAX * 128];   // fp32 einsum out (layer 2)
__device__ float  g_sum[64];
__device__ float  g_sq[64];

// ---------------- packed fp32x2 helpers ----------------
__device__ __forceinline__ u64 pk2(float x, float y) {
    u64 r; asm("mov.b64 %0, {%1, %2};" : "=l"(r) : "f"(x), "f"(y)); return r;
}
__device__ __forceinline__ u64 f2fma(u64 a, u64 b, u64 c) {
    u64 d; asm("fma.rn.f32x2 %0, %1, %2, %3;" : "=l"(d) : "l"(a), "l"(b), "l"(c)); return d;
}
__device__ __forceinline__ float2 up2(u64 v) {
    float lo, hi; asm("mov.b64 {%0, %1}, %2;" : "=f"(lo), "=f"(hi) : "l"(v));
    float2 f; f.x = lo; f.y = hi; return f;
}

// ---------------- CSR build ----------------
__global__ void k_hist(const int* __restrict__ rows, int E) {
    int e = blockIdx.x * blockDim.x + threadIdx.x;
    if (e < E) atomicAdd(&g_cnt[rows[e]], 1);
}

__global__ void k_scan(int V) {
    __shared__ int sh[1024];
    __shared__ int s_carry;
    int tid = threadIdx.x;
    if (tid == 0) s_carry = 0;
    __syncthreads();
    for (int base = 0; base < V; base += 1024) {
        int i = base + tid;
        int v = (i < V) ? g_cnt[i] : 0;
        sh[tid] = v;
        __syncthreads();
        for (int off = 1; off < 1024; off <<= 1) {
            int t = (tid >= off) ? sh[tid - off] : 0;
            __syncthreads();
            sh[tid] += t;
            __syncthreads();
        }
        int carry = s_carry;
        if (i < V) g_rowptr[i] = carry + sh[tid] - v;
        __syncthreads();
        if (tid == 1023) s_carry = carry + sh[1023];
        __syncthreads();
    }
    if (threadIdx.x == 0) g_rowptr[V] = s_carry;
}

__global__ void k_fill(const int* __restrict__ rows, const int* __restrict__ cols,
                       const float* __restrict__ vals, int E) {
    int e = blockIdx.x * blockDim.x + threadIdx.x;
    if (e >= E) return;
    int r = rows[e];
    int pos = g_rowptr[r] + atomicAdd(&g_cnt[r], 1);
    g_cols[pos] = cols[e];
    g_vals[pos] = vals[e];
}

// ---------------- BatchNorm stats ----------------
// input x is fp32 (B, C, V): one slab = (b,c) contiguous V floats
__global__ void k_stats_in(const float* __restrict__ x, int V, int C) {
    __shared__ float ss[256], sq[256];
    int slab = blockIdx.y;
    int c = slab % C;
    const float* p = x + (size_t)slab * V;
    float s = 0.f, q = 0.f;
    for (int i = blockIdx.x * blockDim.x + threadIdx.x; i < V; i += gridDim.x * blockDim.x) {
        float t = p[i];
        s += t; q += t * t;
    }
    int tid = threadIdx.x;
    ss[tid] = s; sq[tid] = q;
    __syncthreads();
    for (int o = 128; o > 0; o >>= 1) {
        if (tid < o) { ss[tid] += ss[tid + o]; sq[tid] += sq[tid + o]; }
        __syncthreads();
    }
    if (tid == 0) { atomicAdd(&g_sum[c], ss[0]); atomicAdd(&g_sq[c], sq[0]); }
}

// T is fp16 vertex-major (V, 64, 4) = 128 half2 per vertex; thread -> fixed half2 slot
__global__ void __launch_bounds__(128) k_stats_vm_h(const __half2* __restrict__ T, int V) {
    int t = threadIdx.x;
    float s = 0.f, q = 0.f;
    for (int v = blockIdx.x; v < V; v += gridDim.x) {
        float2 f = __half22float2(T[(size_t)v * 128 + t]);
        s += f.x + f.y;
        q += f.x * f.x + f.y * f.y;
    }
    s += __shfl_xor_sync(0xffffffffu, s, 1);
    q += __shfl_xor_sync(0xffffffffu, q, 1);
    if ((t & 1) == 0) {
        int c = t >> 1;
        atomicAdd(&g_sum[c], s);
        atomicAdd(&g_sq[c], q);
    }
}

// ---------------- BN apply (finalize folded in) ----------------
// normalize + transpose (B,32,V) fp32 -> (V,32,4) fp16 (g_xn) AND fp32 (g_xnf)
__global__ void __launch_bounds__(128) k_apply_in(const float* __restrict__ x,
                                                  const float* __restrict__ gamma,
                                                  const float* __restrict__ beta,
                                                  float invN, int V) {
    __shared__ float sh[32 * 129];
    __shared__ float ssc[32], ssh[32];
    if (threadIdx.x < 32) {
        int c = threadIdx.x;
        float m = g_sum[c] * invN;
        float var = g_sq[c] * invN - m * m;
        float inv = rsqrtf(var + 1e-5f);
        float sc = gamma[c] * inv;
        ssc[c] = sc;
        ssh[c] = beta[c] - sc * m;
    }
    __syncthreads();
    int v0 = blockIdx.x * 32;
    for (int j = threadIdx.x; j < 4096; j += 128) {
        int b = j >> 10;
        int r = j & 1023;
        int c = r >> 5;
        int vl = r & 31;
        int v = v0 + vl;
        float t = 0.f;
        if (v < V) t = x[((size_t)(b * 32 + c)) * V + v];
        sh[vl * 129 + c * 4 + b] = ssc[c] * t + ssh[c];
    }
    __syncthreads();
    for (int j = threadIdx.x; j < 4096; j += 128) {
        int vl = j >> 7;
        int f = j & 127;
        int v = v0 + vl;
        if (v < V) {
            float t = sh[vl * 129 + f];
            size_t idx = (size_t)v * 128 + f;
            g_xn[idx] = __float2half_rn(t);
            g_xnf[idx] = t;
        }
    }
}

// normalize fp16 (V,64,4): i indexes uint2 = 4 halfs of channel (i&63); finalize folded
__global__ void __launch_bounds__(256) k_apply_vm2(uint2* __restrict__ dst,
                                                   const uint2* __restrict__ src,
                                                   const float* __restrict__ gamma,
                                                   const float* __restrict__ beta,
                                                   float invN, int n) {
    __shared__ float ssc[64], ssh[64];
    if (threadIdx.x < 64) {
        int c = threadIdx.x;
        float m = g_sum[c] * invN;
        float var = g_sq[c] * invN - m * m;
        float inv = rsqrtf(var + 1e-5f);
        float sc = gamma[c] * inv;
        ssc[c] = sc;
        ssh[c] = beta[c] - sc * m;
    }
    __syncthreads();
    int i = blockIdx.x * blockDim.x + threadIdx.x;
    if (i >= n) return;
    int c = i & 63;
    float s = ssc[c], h = ssh[c];
    uint2 raw = src[i];
    float2 fa = __half22float2(*(__half2*)&raw.x);
    float2 fb = __half22float2(*(__half2*)&raw.y);
    fa.x = fa.x * s + h; fa.y = fa.y * s + h;
    fb.x = fb.x * s + h; fb.y = fb.y * s + h;
    uint2 o;
    *(__half2*)&o.x = __floats2half2_rn(fa.x, fa.y);
    *(__half2*)&o.y = __floats2half2_rn(fb.x, fb.y);
    dst[i] = o;
}

// ---------------- SpMM fp16: y[row] = alpha * sum_e w_e * x[col_e] + beta * z[row] ----
template <int F>
__global__ void __launch_bounds__(256) k_spmm_h(__half* __restrict__ y,
                                                const __half* __restrict__ x,
                                                const __half* __restrict__ z,
                                                float alpha, float beta, int V) {
    constexpr int HPL = F / 32;   // 4 or 8
    int row = (blockIdx.x * 256 + threadIdx.x) >> 5;
    if (row >= V) return;
    int lane = threadIdx.x & 31;
    const __half* xb = x + lane * HPL;
    int beg = g_rowptr[row], end = g_rowptr[row + 1];
    float acc[HPL];
#pragma unroll
    for (int i = 0; i < HPL; i++) acc[i] = 0.f;

    int e = beg;
    for (; e + 4 <= end; e += 4) {
        int   cc[4];
        float ww[4];
#pragma unroll
        for (int j = 0; j < 4; j++) { cc[j] = g_cols[e + j]; ww[j] = g_vals[e + j]; }
#pragma unroll
        for (int j = 0; j < 4; j++) {
            const __half* p = xb + (size_t)cc[j] * F;
            float w = ww[j];
            if constexpr (HPL == 8) {
                uint4 raw = *(const uint4*)p;
                float2 f;
                f = __half22float2(*(__half2*)&raw.x); acc[0] += w * f.x; acc[1] += w * f.y;
                f = __half22float2(*(__half2*)&raw.y); acc[2] += w * f.x; acc[3] += w * f.y;
                f = __half22float2(*(__half2*)&raw.z); acc[4] += w * f.x; acc[5] += w * f.y;
                f = __half22float2(*(__half2*)&raw.w); acc[6] += w * f.x; acc[7] += w * f.y;
            } else {
                uint2 raw = *(const uint2*)p;
                float2 f;
                f = __half22float2(*(__half2*)&raw.x); acc[0] += w * f.x; acc[1] += w * f.y;
                f = __half22float2(*(__half2*)&raw.y); acc[2] += w * f.x; acc[3] += w * f.y;
            }
        }
    }
    for (; e < end; e++) {
        int c0 = g_cols[e];
        float w = g_vals[e];
        const __half* p = xb + (size_t)c0 * F;
        if constexpr (HPL == 8) {
            uint4 raw = *(const uint4*)p;
            float2 f;
            f = __half22float2(*(__half2*)&raw.x); acc[0] += w * f.x; acc[1] += w * f.y;
            f = __half22float2(*(__half2*)&raw.y); acc[2] += w * f.x; acc[3] += w * f.y;
            f = __half22float2(*(__half2*)&raw.z); acc[4] += w * f.x; acc[5] += w * f.y;
            f = __half22float2(*(__half2*)&raw.w); acc[6] += w * f.x; acc[7] += w * f.y;
        } else {
            uint2 raw = *(const uint2*)p;
            float2 f;
            f = __half22float2(*(__half2*)&raw.x); acc[0] += w * f.x; acc[1] += w * f.y;
            f = __half22float2(*(__half2*)&raw.y); acc[2] += w * f.x; acc[3] += w * f.y;
        }
    }

    size_t oi = (size_t)row * F + lane * HPL;
    if (beta != 0.f) {
#pragma unroll
        for (int i = 0; i < HPL; i += 2) {
            float2 f = __half22float2(*(const __half2*)(z + oi + i));
            acc[i]     = alpha * acc[i]     + beta * f.x;
            acc[i + 1] = alpha * acc[i + 1] + beta * f.y;
        }
    } else if (alpha != 1.f) {
#pragma unroll
        for (int i = 0; i < HPL; i++) acc[i] *= alpha;
    }
    if constexpr (HPL == 8) {
        uint4 o;
        *(__half2*)&o.x = __floats2half2_rn(acc[0], acc[1]);
        *(__half2*)&o.y = __floats2half2_rn(acc[2], acc[3]);
        *(__half2*)&o.z = __floats2half2_rn(acc[4], acc[5]);
        *(__half2*)&o.w = __floats2half2_rn(acc[6], acc[7]);
        *(uint4*)(y + oi) = o;
    } else {
        uint2 o;
        *(__half2*)&o.x = __floats2half2_rn(acc[0], acc[1]);
        *(__half2*)&o.y = __floats2half2_rn(acc[2], acc[3]);
        *(uint2*)(y + oi) = o;
    }
}

// ---------------- paired einsum with packed fp32x2 FMA -------------------------------
// OUT[v][o][b] (+)= sum_c XA[v][c][b]*wA[c][o] + XB[v][c][b]*wB[c][o]
// acc[o2][b] packs outputs (og+2*o2, og+2*o2+1); weight pairs read packed from shared.
template <int CIN, int COUT, bool INIT, bool RELU, typename OT>
__global__ void __launch_bounds__(128) k_ein2p(OT* __restrict__ out,
                                               const __half* __restrict__ XA,
                                               const __half* __restrict__ XB,
                                               const float* __restrict__ wA,
                                               const float* __restrict__ wB,
                                               const float* __restrict__ bias, int V) {
    constexpr int TPV = COUT / 8;
    constexpr int VPB = 128 / TPV;
    __shared__ float swA[CIN * COUT];
    __shared__ float swB[CIN * COUT];
    __shared__ float sbias[COUT];
    for (int i = threadIdx.x; i < CIN * COUT; i += 128) { swA[i] = wA[i]; swB[i] = wB[i]; }
    if (INIT) for (int i = threadIdx.x; i < COUT; i += 128) sbias[i] = bias[i];
    __syncthreads();
    int v = blockIdx.x * VPB + threadIdx.x / TPV;
    if (v >= V) return;
    int og = (threadIdx.x % TPV) * 8;

    const uint2* xa = (const uint2*)(XA + (size_t)v * CIN * 4);
    const uint2* xb = (const uint2*)(XB + (size_t)v * CIN * 4);
    u64 acc[4][4];
#pragma unroll
    for (int i = 0; i < 4; i++)
#pragma unroll
        for (int j = 0; j < 4; j++) acc[i][j] = 0ull;   // (0.f, 0.f)

#pragma unroll 2
    for (int c = 0; c < CIN; c++) {
        uint2 ra = __ldg(xa + c);
        uint2 rb = __ldg(xb + c);
        float2 a01 = __half22float2(*(__half2*)&ra.x);
        float2 a23 = __half22float2(*(__half2*)&ra.y);
        float2 b01 = __half22float2(*(__half2*)&rb.x);
        float2 b23 = __half22float2(*(__half2*)&rb.y);
        u64 Ad[4] = {pk2(a01.x, a01.x), pk2(a01.y, a01.y), pk2(a23.x, a23.x), pk2(a23.y, a23.y)};
        u64 Bd[4] = {pk2(b01.x, b01.x), pk2(b01.y, b01.y), pk2(b23.x, b23.x), pk2(b23.y, b23.y)};
        const u64* wpA = (const u64*)&swA[c * COUT + og];   // 32B aligned
        const u64* wpB = (const u64*)&swB[c * COUT + og];
#pragma unroll
        for (int o2 = 0; o2 < 4; o2++) {
            u64 wa = wpA[o2];
            u64 wb = wpB[o2];
#pragma unroll
            for (int b = 0; b < 4; b++) {
                acc[o2][b] = f2fma(Ad[b], wa, acc[o2][b]);
                acc[o2][b] = f2fma(Bd[b], wb, acc[o2][b]);
            }
        }
    }

    float r[8][4];
#pragma unroll
    for (int o2 = 0; o2 < 4; o2++)
#pragma unroll
        for (int b = 0; b < 4; b++) {
            float2 p = up2(acc[o2][b]);
            r[2 * o2][b] = p.x;
            r[2 * o2 + 1][b] = p.y;
        }

    if constexpr (sizeof(OT) == 2) {
        __half2* o2p = (__half2*)((__half*)out + (size_t)v * COUT * 4 + og * 4);
#pragma unroll
        for (int o = 0; o < 8; o++) {
            float rx = r[o][0], ry = r[o][1], rz = r[o][2], rw = r[o][3];
            if (INIT) {
                float bb = sbias[og + o];
                rx += bb; ry += bb; rz += bb; rw += bb;
            } else {
                float2 p0 = __half22float2(o2p[2 * o]);
                float2 p1 = __half22float2(o2p[2 * o + 1]);
                rx += p0.x; ry += p0.y; rz += p1.x; rw += p1.y;
            }
            if (RELU) {
                rx = fmaxf(rx, 0.f); ry = fmaxf(ry, 0.f);
                rz = fmaxf(rz, 0.f); rw = fmaxf(rw, 0.f);
            }
            o2p[2 * o]     = __floats2half2_rn(rx, ry);
            o2p[2 * o + 1] = __floats2half2_rn(rz, rw);
        }
    } else {
        float4* o4 = (float4*)((float*)out + (size_t)v * COUT * 4 + og * 4);
#pragma unroll
        for (int o = 0; o < 8; o++) {
            float rx = r[o][0], ry = r[o][1], rz = r[o][2], rw = r[o][3];
            if (INIT) {
                float bb = sbias[og + o];
                rx += bb; ry += bb; rz += bb; rw += bb;
            } else {
                float4 p = o4[o];
                rx += p.x; ry += p.y; rz += p.z; rw += p.w;
            }
            if (RELU) {
                rx = fmaxf(rx, 0.f); ry = fmaxf(ry, 0.f);
                rz = fmaxf(rz, 0.f); rw = fmaxf(rw, 0.f);
            }
            o4[o] = make_float4(rx, ry, rz, rw);
        }
    }
}

// ---------------- final residual + relu + transpose to fp32 (B,32,V) ----------------
__global__ void __launch_bounds__(128) k_final(float* __restrict__ out,
                                               const float* __restrict__ R, int V) {
    __shared__ float sh[32 * 129];
    int v0 = blockIdx.x * 32;
    for (int j = threadIdx.x; j < 4096; j += 128) {
        int vl = j >> 7;
        int f = j & 127;
        int v = v0 + vl;
        float t = 0.f;
        if (v < V) {
            size_t idx = (size_t)v * 128 + f;
            t = fmaxf(R[idx] + g_xnf[idx], 0.f);
        }
        sh[vl * 129 + f] = t;
    }
    __syncthreads();
    for (int j = threadIdx.x; j < 4096; j += 128) {
        int b = j >> 10;
        int r = j & 1023;
        int c = r >> 5;
        int vl = r & 31;
        int v = v0 + vl;
        if (v < V) out[((size_t)(b * 32 + c)) * V + v] = sh[vl * 129 + c * 4 + b];
    }
}

// ---------------- host orchestration ----------------
extern "C" void kernel_launch(void* const* d_in, const int* in_sizes, int n_in,
                              void* d_out, int out_size) {
    const float* x        = (const float*)d_in[0];
    const int*   ei       = (const int*)d_in[1];
    const float* lap_vals = (const float*)d_in[2];
    const float* in_bn_g  = (const float*)d_in[3];
    const float* in_bn_b  = (const float*)d_in[4];
    const float* in_w     = (const float*)d_in[5];
    const float* in_b     = (const float*)d_in[6];
    const float* h0_bn_g  = (const float*)d_in[7];
    const float* h0_bn_b  = (const float*)d_in[8];
    const float* h0_w     = (const float*)d_in[9];
    const float* h0_b     = (const float*)d_in[10];
    const float* h1_bn_g  = (const float*)d_in[11];
    const float* h1_bn_b  = (const float*)d_in[12];
    const float* h1_w     = (const float*)d_in[13];
    const float* h1_b     = (const float*)d_in[14];

    const int V = in_sizes[0] / 128;
    const int E = in_sizes[1] / 2;
    const int* rows = ei;
    const int* cols = ei + E;
    const float invN = 1.0f / (4.0f * (float)V);

    __half *xn, *x0, *x1, *x2, *x3, *tb;
    float *of;
    void *cntp, *sump, *sqp;
    cudaGetSymbolAddress((void**)&xn, g_xn);
    cudaGetSymbolAddress((void**)&x0, g_x0);
    cudaGetSymbolAddress((void**)&x1, g_x1);
    cudaGetSymbolAddress((void**)&x2, g_x2);
    cudaGetSymbolAddress((void**)&x3, g_x3);
    cudaGetSymbolAddress((void**)&tb, g_t);
    cudaGetSymbolAddress((void**)&of, g_of);
    cudaGetSymbolAddress(&cntp, g_cnt);
    cudaGetSymbolAddress(&sump, g_sum);
    cudaGetSymbolAddress(&sqp, g_sq);

    const int NBE  = (E + 255) / 256;
    const int NB32 = (V + 31) / 32;
    const int NBW  = (V + 7) / 8;          // one warp per row, 256-thread blocks
    const int NE64 = (V + 15) / 16;
    const int NE32 = (V + 31) / 32;
    const int NAPP = (V * 64 + 255) / 256;

    // ---- CSR build (zeroing via memset nodes; kernel launch #1..#3) ----
    cudaMemsetAsync(cntp, 0, (size_t)V * 4);
    k_hist<<<NBE, 256>>>(rows, E);
    k_scan<<<1, 1024>>>(V);
    cudaMemsetAsync(cntp, 0, (size_t)V * 4);
    k_fill<<<NBE, 256>>>(rows, cols, lap_vals, E);

    // ---- layer 0: BN(32) + Cheb 32->64 ----
    cudaMemsetAsync(sump, 0, 64 * 4);
    cudaMemsetAsync(sqp, 0, 64 * 4);
    k_stats_in<<<dim3(8, 128), 256>>>(x, V, 32);                         // launch #4
    k_apply_in<<<NB32, 128>>>(x, in_bn_g, in_bn_b, invN, V);             // launch #5

    k_spmm_h<128><<<NBW, 256>>>(x1, xn, nullptr, 1.f, 0.f, V);           // launch #6 (profiled)
    k_spmm_h<128><<<NBW, 256>>>(x2, x1, xn, 2.f, -1.f, V);
    k_ein2p<32, 64, true, false, __half><<<NE64, 128>>>(tb, xn, x1,
        in_w + 0 * 2048, in_w + 1 * 2048, in_b, V);
    k_spmm_h<128><<<NBW, 256>>>(x3, x2, x1, 2.f, -1.f, V);
    k_ein2p<32, 64, false, true, __half><<<NE64, 128>>>(tb, x2, x3,
        in_w + 2 * 2048, in_w + 3 * 2048, nullptr, V);

    // ---- layer 1: BN(64) + Cheb 64->64 ----
    cudaMemsetAsync(sump, 0, 64 * 4);
    cudaMemsetAsync(sqp, 0, 64 * 4);
    k_stats_vm_h<<<1024, 128>>>((const __half2*)tb, V);
    k_apply_vm2<<<NAPP, 256>>>((uint2*)x0, (const uint2*)tb, h0_bn_g, h0_bn_b, invN, V * 64);

    k_spmm_h<256><<<NBW, 256>>>(x1, x0, nullptr, 1.f, 0.f, V);
    k_spmm_h<256><<<NBW, 256>>>(x2, x1, x0, 2.f, -1.f, V);
    k_ein2p<64, 64, true, false, __half><<<NE64, 128>>>(tb, x0, x1,
        h0_w + 0 * 4096, h0_w + 1 * 4096, h0_b, V);
    k_spmm_h<256><<<NBW, 256>>>(x3, x2, x1, 2.f, -1.f, V);
    k_ein2p<64, 64, false, true, __half><<<NE64, 128>>>(tb, x2, x3,
        h0_w + 2 * 4096, h0_w + 3 * 4096, nullptr, V);

    // ---- layer 2: BN(64) + Cheb 64->32, fp32 output, no relu ----
    cudaMemsetAsync(sump, 0, 64 * 4);
    cudaMemsetAsync(sqp, 0, 64 * 4);
    k_stats_vm_h<<<1024, 128>>>((const __half2*)tb, V);
    k_apply_vm2<<<NAPP, 256>>>((uint2*)x0, (const uint2*)tb, h1_bn_g, h1_bn_b, invN, V * 64);

    k_spmm_h<256><<<NBW, 256>>>(x1, x0, nullptr, 1.f, 0.f, V);
    k_spmm_h<256><<<NBW, 256>>>(x2, x1, x0, 2.f, -1.f, V);
    k_ein2p<64, 32, true, false, float><<<NE32, 128>>>(of, x0, x1,
        h1_w + 0 * 2048, h1_w + 1 * 2048, h1_b, V);
    k_spmm_h<256><<<NBW, 256>>>(x3, x2, x1, 2.f, -1.f, V);
    k_ein2p<64, 32, false, false, float><<<NE32, 128>>>(of, x2, x3,
        h1_w + 2 * 2048, h1_w + 3 * 2048, nullptr, V);

    // ---- residual + relu + transpose to (B,32,V) fp32 ----
    k_final<<<NB32, 128>>>((float*)d_out, of, V);
    (void)n_in; (void)out_size;
}

// round 8
// speedup vs baseline: 1.5676x; 1.5676x over previous
#include <cuda_runtime.h>
#include <cuda_fp16.h>
#include <cstdint>

#define VMAX 100000
#define EMAX 1600000

// ---------------- device scratch (no allocations allowed) ----------------
__device__ int    g_rowptr[VMAX + 1];
__device__ int    g_cnt[VMAX];
__device__ int    g_cols[EMAX];
__device__ float  g_vals[EMAX];
__device__ __half g_xn [(size_t)VMAX * 128];  // BN'ed input (v,b,c) fp16 (layer0 X0)
__device__ float  g_xnf[(size_t)VMAX * 128];  // BN'ed input fp32 (residual path)
__device__ __half g_x0[(size_t)VMAX * 256];
__device__ __half g_x1[(size_t)VMAX * 256];
__device__ __half g_x2[(size_t)VMAX * 256];
__device__ __half g_x3[(size_t)VMAX * 256];
__device__ __half g_t [(size_t)VMAX * 256];   // fp16 einsum out (layers 0,1), (v,b,c)
__device__ float  g_of[(size_t)VMAX * 128];   // fp32 einsum out (layer 2), (v,b,o)
__device__ float  g_stats[128];               // [0:64) sum, [64:128) sumsq
__device__ __half g_w0[4 * 64 * 32];          // layer0 W^T (k,o,c) fp16: 4 x 64 x 32
__device__ __half g_w1[4 * 64 * 64];          // layer1: 4 x 64 x 64
__device__ __half g_w2[4 * 32 * 64];          // layer2: 4 x 32 x 64

// ---------------- CSR build ----------------
__global__ void k_hist(const int* __restrict__ rows, int E) {
    int e = blockIdx.x * blockDim.x + threadIdx.x;
    if (e < E) atomicAdd(&g_cnt[rows[e]], 1);
}

// exclusive scan of g_cnt -> g_rowptr; also re-zeroes g_cnt for k_fill
__global__ void k_scan(int V) {
    __shared__ int sh[1024];
    __shared__ int s_carry;
    int tid = threadIdx.x;
    if (tid == 0) s_carry = 0;
    __syncthreads();
    for (int base = 0; base < V; base += 1024) {
        int i = base + tid;
        int v = 0;
        if (i < V) { v = g_cnt[i]; g_cnt[i] = 0; }
        sh[tid] = v;
        __syncthreads();
        for (int off = 1; off < 1024; off <<= 1) {
            int t = (tid >= off) ? sh[tid - off] : 0;
            __syncthreads();
            sh[tid] += t;
            __syncthreads();
        }
        int carry = s_carry;
        if (i < V) g_rowptr[i] = carry + sh[tid] - v;
        __syncthreads();
        if (tid == 1023) s_carry = carry + sh[1023];
        __syncthreads();
    }
    if (threadIdx.x == 0) g_rowptr[V] = s_carry;
}

__global__ void k_fill(const int* __restrict__ rows, const int* __restrict__ cols,
                       const float* __restrict__ vals, int E) {
    int e = blockIdx.x * blockDim.x + threadIdx.x;
    if (e >= E) return;
    int r = rows[e];
    int pos = g_rowptr[r] + atomicAdd(&g_cnt[r], 1);
    g_cols[pos] = cols[e];
    g_vals[pos] = vals[e];
}

// ---------------- weight convert/transpose: w(k,c,o) fp32 -> wt(k,o,c) fp16 ----------
__global__ void k_wconv(const float* __restrict__ w0, const float* __restrict__ w1,
                        const float* __restrict__ w2) {
    int i0 = blockIdx.x * blockDim.x + threadIdx.x;
    int stride = gridDim.x * blockDim.x;
    for (int i = i0; i < 4 * 32 * 64; i += stride) {   // layer0: CIN=32, COUT=64
        int k = i / (32 * 64), r = i % (32 * 64);
        int o = r / 32, c = r % 32;
        g_w0[i] = __float2half_rn(w0[(k * 32 + c) * 64 + o]);
    }
    for (int i = i0; i < 4 * 64 * 64; i += stride) {   // layer1
        int k = i / (64 * 64), r = i % (64 * 64);
        int o = r / 64, c = r % 64;
        g_w1[i] = __float2half_rn(w1[(k * 64 + c) * 64 + o]);
    }
    for (int i = i0; i < 4 * 32 * 64; i += stride) {   // layer2: CIN=64, COUT=32
        int k = i / (32 * 64), r = i % (32 * 64);
        int o = r / 64, c = r % 64;
        g_w2[i] = __float2half_rn(w2[(k * 64 + c) * 32 + o]);
    }
}

// ---------------- BatchNorm stats ----------------
// input x is fp32 (B, C, V)
__global__ void k_stats_in(const float* __restrict__ x, int V, int C) {
    __shared__ float ss[256], sq[256];
    int slab = blockIdx.y;
    int c = slab % C;
    const float* p = x + (size_t)slab * V;
    float s = 0.f, q = 0.f;
    for (int i = blockIdx.x * blockDim.x + threadIdx.x; i < V; i += gridDim.x * blockDim.x) {
        float t = p[i];
        s += t; q += t * t;
    }
    int tid = threadIdx.x;
    ss[tid] = s; sq[tid] = q;
    __syncthreads();
    for (int o = 128; o > 0; o >>= 1) {
        if (tid < o) { ss[tid] += ss[tid + o]; sq[tid] += sq[tid + o]; }
        __syncthreads();
    }
    if (tid == 0) { atomicAdd(&g_stats[c], ss[0]); atomicAdd(&g_stats[64 + c], sq[0]); }
}

// T is fp16 (v, b, c) c in [0,64): 128 half2 per vertex; slot t covers halfs 2t,2t+1
__global__ void __launch_bounds__(128) k_stats_vm(const __half2* __restrict__ T, int V) {
    __shared__ float bs[64], bq[64];
    int t = threadIdx.x;
    if (t < 64) { bs[t] = 0.f; bq[t] = 0.f; }
    __syncthreads();
    float s0 = 0.f, q0 = 0.f, s1 = 0.f, q1 = 0.f;
    for (int v = blockIdx.x; v < V; v += gridDim.x) {
        float2 f = __half22float2(T[(size_t)v * 128 + t]);
        s0 += f.x; q0 += f.x * f.x;
        s1 += f.y; q1 += f.y * f.y;
    }
    int c0 = (2 * t) & 63;
    atomicAdd(&bs[c0], s0);     atomicAdd(&bq[c0], q0);
    atomicAdd(&bs[c0 + 1], s1); atomicAdd(&bq[c0 + 1], q1);
    __syncthreads();
    if (t < 64) {
        atomicAdd(&g_stats[t], bs[t]);
        atomicAdd(&g_stats[64 + t], bq[t]);
    }
}

// ---------------- BN apply ----------------
// normalize + transpose (B,32,V) fp32 -> (v, b, c) fp16 (g_xn) AND fp32 (g_xnf)
// slab index f = b*32+c is exactly the per-vertex half index.
__global__ void __launch_bounds__(128) k_apply_in(const float* __restrict__ x,
                                                  const float* __restrict__ gamma,
                                                  const float* __restrict__ beta,
                                                  float invN, int V) {
    __shared__ float sh[32 * 129];
    __shared__ float ssc[32], ssh[32];
    if (threadIdx.x < 32) {
        int c = threadIdx.x;
        float m = g_stats[c] * invN;
        float var = g_stats[64 + c] * invN - m * m;
        float inv = rsqrtf(var + 1e-5f);
        float sc = gamma[c] * inv;
        ssc[c] = sc;
        ssh[c] = beta[c] - sc * m;
    }
    __syncthreads();
    int v0 = blockIdx.x * 32;
    for (int j = threadIdx.x; j < 4096; j += 128) {
        int f = j >> 5;          // slab = b*32+c
        int vl = j & 31;
        int c = f & 31;
        int v = v0 + vl;
        float t = 0.f;
        if (v < V) t = x[(size_t)f * V + v];
        sh[vl * 129 + f] = ssc[c] * t + ssh[c];
    }
    __syncthreads();
    for (int j = threadIdx.x; j < 4096; j += 128) {
        int vl = j >> 7;
        int f = j & 127;
        int v = v0 + vl;
        if (v < V) {
            float t = sh[vl * 129 + f];
            size_t idx = (size_t)v * 128 + f;
            g_xn[idx] = __float2half_rn(t);
            g_xnf[idx] = t;
        }
    }
}

// normalize fp16 (v,b,c) c in [0,64): uint2 i = halfs 4i..4i+3 = channels c0..c0+3
__global__ void __launch_bounds__(256) k_apply_vm(uint2* __restrict__ dst,
                                                  const uint2* __restrict__ src,
                                                  const float* __restrict__ gamma,
                                                  const float* __restrict__ beta,
                                                  float invN, int n) {
    __shared__ float ssc[64], ssh[64];
    if (threadIdx.x < 64) {
        int c = threadIdx.x;
        float m = g_stats[c] * invN;
        float var = g_stats[64 + c] * invN - m * m;
        float inv = rsqrtf(var + 1e-5f);
        float sc = gamma[c] * inv;
        ssc[c] = sc;
        ssh[c] = beta[c] - sc * m;
    }
    __syncthreads();
    int i = blockIdx.x * blockDim.x + threadIdx.x;
    if (i >= n) return;
    int c0 = (i & 15) * 4;
    float4 s4 = *(float4*)&ssc[c0];
    float4 h4 = *(float4*)&ssh[c0];
    uint2 raw = src[i];
    float2 fa = __half22float2(*(__half2*)&raw.x);
    float2 fb = __half22float2(*(__half2*)&raw.y);
    fa.x = fa.x * s4.x + h4.x; fa.y = fa.y * s4.y + h4.y;
    fb.x = fb.x * s4.z + h4.z; fb.y = fb.y * s4.w + h4.w;
    uint2 o;
    *(__half2*)&o.x = __floats2half2_rn(fa.x, fa.y);
    *(__half2*)&o.y = __floats2half2_rn(fb.x, fb.y);
    dst[i] = o;
}

// ---------------- SpMM fp16 (layout-agnostic): y = alpha*L*x + beta*z ----------------
template <int F>
__global__ void __launch_bounds__(256) k_spmm_h(__half* __restrict__ y,
                                                const __half* __restrict__ x,
                                                const __half* __restrict__ z,
                                                float alpha, float beta, int V) {
    constexpr int HPL = F / 32;   // 4 or 8
    int row = (blockIdx.x * 256 + threadIdx.x) >> 5;
    if (row >= V) return;
    int lane = threadIdx.x & 31;
    const __half* xb = x + lane * HPL;
    int beg = g_rowptr[row], end = g_rowptr[row + 1];
    float acc[HPL];
#pragma unroll
    for (int i = 0; i < HPL; i++) acc[i] = 0.f;

    int e = beg;
    for (; e + 4 <= end; e += 4) {
        int   cc[4];
        float ww[4];
#pragma unroll
        for (int j = 0; j < 4; j++) { cc[j] = g_cols[e + j]; ww[j] = g_vals[e + j]; }
#pragma unroll
        for (int j = 0; j < 4; j++) {
            const __half* p = xb + (size_t)cc[j] * F;
            float w = ww[j];
            if constexpr (HPL == 8) {
                uint4 raw = *(const uint4*)p;
                float2 f;
                f = __half22float2(*(__half2*)&raw.x); acc[0] += w * f.x; acc[1] += w * f.y;
                f = __half22float2(*(__half2*)&raw.y); acc[2] += w * f.x; acc[3] += w * f.y;
                f = __half22float2(*(__half2*)&raw.z); acc[4] += w * f.x; acc[5] += w * f.y;
                f = __half22float2(*(__half2*)&raw.w); acc[6] += w * f.x; acc[7] += w * f.y;
            } else {
                uint2 raw = *(const uint2*)p;
                float2 f;
                f = __half22float2(*(__half2*)&raw.x); acc[0] += w * f.x; acc[1] += w * f.y;
                f = __half22float2(*(__half2*)&raw.y); acc[2] += w * f.x; acc[3] += w * f.y;
            }
        }
    }
    for (; e < end; e++) {
        int c0 = g_cols[e];
        float w = g_vals[e];
        const __half* p = xb + (size_t)c0 * F;
        if constexpr (HPL == 8) {
            uint4 raw = *(const uint4*)p;
            float2 f;
            f = __half22float2(*(__half2*)&raw.x); acc[0] += w * f.x; acc[1] += w * f.y;
            f = __half22float2(*(__half2*)&raw.y); acc[2] += w * f.x; acc[3] += w * f.y;
            f = __half22float2(*(__half2*)&raw.z); acc[4] += w * f.x; acc[5] += w * f.y;
            f = __half22float2(*(__half2*)&raw.w); acc[6] += w * f.x; acc[7] += w * f.y;
        } else {
            uint2 raw = *(const uint2*)p;
            float2 f;
            f = __half22float2(*(__half2*)&raw.x); acc[0] += w * f.x; acc[1] += w * f.y;
            f = __half22float2(*(__half2*)&raw.y); acc[2] += w * f.x; acc[3] += w * f.y;
        }
    }

    size_t oi = (size_t)row * F + lane * HPL;
    if (beta != 0.f) {
#pragma unroll
        for (int i = 0; i < HPL; i += 2) {
            float2 f = __half22float2(*(const __half2*)(z + oi + i));
            acc[i]     = alpha * acc[i]     + beta * f.x;
            acc[i + 1] = alpha * acc[i + 1] + beta * f.y;
        }
    } else if (alpha != 1.f) {
#pragma unroll
        for (int i = 0; i < HPL; i++) acc[i] *= alpha;
    }
    if constexpr (HPL == 8) {
        uint4 o;
        *(__half2*)&o.x = __floats2half2_rn(acc[0], acc[1]);
        *(__half2*)&o.y = __floats2half2_rn(acc[2], acc[3]);
        *(__half2*)&o.z = __floats2half2_rn(acc[4], acc[5]);
        *(__half2*)&o.w = __floats2half2_rn(acc[6], acc[7]);
        *(uint4*)(y + oi) = o;
    } else {
        uint2 o;
        *(__half2*)&o.x = __floats2half2_rn(acc[0], acc[1]);
        *(__half2*)&o.y = __floats2half2_rn(acc[2], acc[3]);
        *(uint2*)(y + oi) = o;
    }
}

// ---------------- tensor-core einsum ----------------------------------------------
// out[m = (v,b)][o] = sum_{k,c} Xk[m][c] * W[k][c][o] + bias[o], optional ReLU.
// A = X rows (row-major, fp16), B = Wt (k,o,c) fp16 via manual col-major fragments.
// CTA: 128 threads = 4 warps, M-tile 64 rows, N = COUT.
template <int CIN, int COUT, bool RELU, typename OT>
__global__ void __launch_bounds__(128) k_einmma(OT* __restrict__ out,
                                                const __half* __restrict__ X0,
                                                const __half* __restrict__ X1,
                                                const __half* __restrict__ X2,
                                                const __half* __restrict__ X3,
                                                const __half* __restrict__ Wt,
                                                const float* __restrict__ bias,
                                                int rows4) {
    constexpr int CHUNKS = 4 * CIN / 16;
    constexpr int NT = COUT / 8;
    constexpr int WROW = CIN + 2;          // padded smem row (halfs), bank-conflict free
    __shared__ __half sW[4 * COUT * WROW];
    __shared__ float  sb[COUT];
    __shared__ __half sA[4][16 * 24];      // per warp: 16 rows x 16 halfs, stride 24

    // stage transposed weights (pad rows)
    for (int i = threadIdx.x; i < 4 * COUT * CIN / 2; i += 128) {
        int row = (2 * i) / CIN;
        int c = (2 * i) % CIN;
        *(__half2*)&sW[row * WROW + c] = *(const __half2*)&Wt[2 * i];
    }
    for (int i = threadIdx.x; i < COUT; i += 128) sb[i] = bias[i];
    __syncthreads();

    int warp = threadIdx.x >> 5;
    int lane = threadIdx.x & 31;
    int mbase = blockIdx.x * 64 + warp * 16;

    const __half* Xs[4] = {X0, X1, X2, X3};

    float acc[NT][4];
#pragma unroll
    for (int n = 0; n < NT; n++)
#pragma unroll
        for (int j = 0; j < 4; j++) acc[n][j] = 0.f;

    // smem addresses
    uint32_t sa_base;
    {
        const void* p = &sA[warp][0];
        asm("{ .reg .u64 t; cvta.to.shared.u64 t, %1; cvt.u32.u64 %0, t; }"
            : "=r"(sa_base) : "l"(p));
    }
    int ldrow = lane & 15;
    int ldhi = lane >> 4;
    uint32_t lm_addr = sa_base + (ldrow * 24 + ldhi * 8) * 2;

    int srow = lane >> 1;                // staging: row, 16B half-row
    int soff = (lane & 1) * 8;
    int gr = mbase + srow;
    bool grok = (gr < rows4);

    int g = lane >> 2;                   // mma group id (row / n)
    int t2 = (lane & 3) * 2;             // 2t

#pragma unroll
    for (int ch = 0; ch < CHUNKS; ch++) {
        const int kbuf = ch / (CIN / 16);
        const int c0 = (ch % (CIN / 16)) * 16;
        // stage A tile (each warp its own 16 rows)
        uint4 av = make_uint4(0, 0, 0, 0);
        if (grok) av = *(const uint4*)(Xs[kbuf] + (size_t)gr * CIN + c0 + soff);
        __syncwarp();
        *(uint4*)&sA[warp][srow * 24 + soff] = av;
        __syncwarp();
        // ldmatrix x4 -> A fragments
        uint32_t a0, a1, a2, a3;
        asm volatile("ldmatrix.sync.aligned.m8n8.x4.shared.b16 {%0,%1,%2,%3}, [%4];"
                     : "=r"(a0), "=r"(a1), "=r"(a2), "=r"(a3) : "r"(lm_addr));
#pragma unroll
        for (int nt = 0; nt < NT; nt++) {
            int o = nt * 8 + g;
            const __half* wrow = &sW[(kbuf * COUT + o) * WROW + c0 + t2];
            uint32_t b0 = *(const uint32_t*)wrow;         // W[c0+2t][o], W[c0+2t+1][o]
            uint32_t b1 = *(const uint32_t*)(wrow + 8);   // +8 in k
            asm volatile(
                "mma.sync.aligned.m16n8k16.row.col.f32.f16.f16.f32 "
                "{%0,%1,%2,%3}, {%4,%5,%6,%7}, {%8,%9}, {%0,%1,%2,%3};"
                : "+f"(acc[nt][0]), "+f"(acc[nt][1]), "+f"(acc[nt][2]), "+f"(acc[nt][3])
                : "r"(a0), "r"(a1), "r"(a2), "r"(a3), "r"(b0), "r"(b1));
        }
    }

    // epilogue: D[g][2t],[2t+1] and D[g+8][2t],[2t+1]
    int r0 = mbase + g;
    int r1 = r0 + 8;
#pragma unroll
    for (int nt = 0; nt < NT; nt++) {
        int o0 = nt * 8 + t2;
        float bb0 = sb[o0], bb1 = sb[o0 + 1];
        float v00 = acc[nt][0] + bb0, v01 = acc[nt][1] + bb1;
        float v10 = acc[nt][2] + bb0, v11 = acc[nt][3] + bb1;
        if (RELU) {
            v00 = fmaxf(v00, 0.f); v01 = fmaxf(v01, 0.f);
            v10 = fmaxf(v10, 0.f); v11 = fmaxf(v11, 0.f);
        }
        if constexpr (sizeof(OT) == 2) {
            if (r0 < rows4)
                *(__half2*)((__half*)out + (size_t)r0 * COUT + o0) = __floats2half2_rn(v00, v01);
            if (r1 < rows4)
                *(__half2*)((__half*)out + (size_t)r1 * COUT + o0) = __floats2half2_rn(v10, v11);
        } else {
            if (r0 < rows4)
                *(float2*)((float*)out + (size_t)r0 * COUT + o0) = make_float2(v00, v01);
            if (r1 < rows4)
                *(float2*)((float*)out + (size_t)r1 * COUT + o0) = make_float2(v10, v11);
        }
    }
}

// ---------------- final residual + relu + transpose to fp32 (B,32,V) ----------------
// g_of and g_xnf are (v, b, c): half-index f = b*32+c = output slab index.
__global__ void __launch_bounds__(128) k_final(float* __restrict__ out,
                                               const float* __restrict__ R, int V) {
    __shared__ float sh[32 * 129];
    int v0 = blockIdx.x * 32;
    for (int j = threadIdx.x; j < 4096; j += 128) {
        int vl = j >> 7;
        int f = j & 127;
        int v = v0 + vl;
        float t = 0.f;
        if (v < V) {
            size_t idx = (size_t)v * 128 + f;
            t = fmaxf(R[idx] + g_xnf[idx], 0.f);
        }
        sh[vl * 129 + f] = t;
    }
    __syncthreads();
    for (int j = threadIdx.x; j < 4096; j += 128) {
        int f = j >> 5;
        int vl = j & 31;
        int v = v0 + vl;
        if (v < V) out[(size_t)f * V + v] = sh[vl * 129 + f];
    }
}

// ---------------- host orchestration ----------------
extern "C" void kernel_launch(void* const* d_in, const int* in_sizes, int n_in,
                              void* d_out, int out_size) {
    const float* x        = (const float*)d_in[0];
    const int*   ei       = (const int*)d_in[1];
    const float* lap_vals = (const float*)d_in[2];
    const float* in_bn_g  = (const float*)d_in[3];
    const float* in_bn_b  = (const float*)d_in[4];
    const float* in_w     = (const float*)d_in[5];
    const float* in_b     = (const float*)d_in[6];
    const float* h0_bn_g  = (const float*)d_in[7];
    const float* h0_bn_b  = (const float*)d_in[8];
    const float* h0_w     = (const float*)d_in[9];
    const float* h0_b     = (const float*)d_in[10];
    const float* h1_bn_g  = (const float*)d_in[11];
    const float* h1_bn_b  = (const float*)d_in[12];
    const float* h1_w     = (const float*)d_in[13];
    const float* h1_b     = (const float*)d_in[14];

    const int V = in_sizes[0] / 128;
    const int E = in_sizes[1] / 2;
    const int rows4 = 4 * V;
    const int* rows = ei;
    const int* cols = ei + E;
    const float invN = 1.0f / (4.0f * (float)V);

    __half *xn, *x0, *x1, *x2, *x3, *tb, *w0, *w1, *w2;
    float *of;
    void *cntp, *statp;
    cudaGetSymbolAddress((void**)&xn, g_xn);
    cudaGetSymbolAddress((void**)&x0, g_x0);
    cudaGetSymbolAddress((void**)&x1, g_x1);
    cudaGetSymbolAddress((void**)&x2, g_x2);
    cudaGetSymbolAddress((void**)&x3, g_x3);
    cudaGetSymbolAddress((void**)&tb, g_t);
    cudaGetSymbolAddress((void**)&of, g_of);
    cudaGetSymbolAddress((void**)&w0, g_w0);
    cudaGetSymbolAddress((void**)&w1, g_w1);
    cudaGetSymbolAddress((void**)&w2, g_w2);
    cudaGetSymbolAddress(&cntp, g_cnt);
    cudaGetSymbolAddress(&statp, g_stats);

    const int NBE  = (E + 255) / 256;
    const int NB32 = (V + 31) / 32;
    const int NBW  = (V + 7) / 8;            // spmm: one warp per row
    const int NEM  = (rows4 + 63) / 64;      // einmma M-blocks
    const int NAPP = (V * 64 + 255) / 256;

    // ---- CSR build ----
    cudaMemsetAsync(cntp, 0, (size_t)V * 4);
    k_hist<<<NBE, 256>>>(rows, E);
    k_scan<<<1, 1024>>>(V);                  // also re-zeroes g_cnt
    k_fill<<<NBE, 256>>>(rows, cols, lap_vals, E);
    k_wconv<<<32, 256>>>(in_w, h0_w, h1_w);

    // ---- layer 0: BN(32) + Cheb 32->64 ----
    cudaMemsetAsync(statp, 0, 128 * 4);
    k_stats_in<<<dim3(8, 128), 256>>>(x, V, 32);
    k_apply_in<<<NB32, 128>>>(x, in_bn_g, in_bn_b, invN, V);

    k_spmm_h<128><<<NBW, 256>>>(x1, xn, nullptr, 1.f, 0.f, V);
    k_spmm_h<128><<<NBW, 256>>>(x2, x1, xn, 2.f, -1.f, V);
    k_spmm_h<128><<<NBW, 256>>>(x3, x2, x1, 2.f, -1.f, V);
    k_einmma<32, 64, true, __half><<<NEM, 128>>>(tb, xn, x1, x2, x3, w0, in_b, rows4);

    // ---- layer 1: BN(64) + Cheb 64->64 ----
    cudaMemsetAsync(statp, 0, 128 * 4);
    k_stats_vm<<<1024, 128>>>((const __half2*)tb, V);
    k_apply_vm<<<NAPP, 256>>>((uint2*)x0, (const uint2*)tb, h0_bn_g, h0_bn_b, invN, V * 64);

    k_spmm_h<256><<<NBW, 256>>>(x1, x0, nullptr, 1.f, 0.f, V);
    k_spmm_h<256><<<NBW, 256>>>(x2, x1, x0, 2.f, -1.f, V);
    k_spmm_h<256><<<NBW, 256>>>(x3, x2, x1, 2.f, -1.f, V);
    k_einmma<64, 64, true, __half><<<NEM, 128>>>(tb, x0, x1, x2, x3, w1, h0_b, rows4);

    // ---- layer 2: BN(64) + Cheb 64->32, fp32 out, no relu ----
    cudaMemsetAsync(statp, 0, 128 * 4);
    k_stats_vm<<<1024, 128>>>((const __half2*)tb, V);
    k_apply_vm<<<NAPP, 256>>>((uint2*)x0, (const uint2*)tb, h1_bn_g, h1_bn_b, invN, V * 64);

    k_spmm_h<256><<<NBW, 256>>>(x1, x0, nullptr, 1.f, 0.f, V);
    k_spmm_h<256><<<NBW, 256>>>(x2, x1, x0, 2.f, -1.f, V);
    k_spmm_h<256><<<NBW, 256>>>(x3, x2, x1, 2.f, -1.f, V);
    k_einmma<64, 32, false, float><<<NEM, 128>>>(of, x0, x1, x2, x3, w2, h1_b, rows4);

    // ---- residual + relu + transpose to (B,32,V) fp32 ----
    k_final<<<NB32, 128>>>((float*)d_out, of, V);
    (void)n_in; (void)out_size;
}

// round 9
// speedup vs baseline: 1.5814x; 1.0088x over previous
#include <cuda_runtime.h>
#include <cuda_fp16.h>
#include <cstdint>

#define VMAX 100000
#define EMAX 1600000

// ---------------- device scratch (no allocations allowed) ----------------
__device__ int    g_rowptr[VMAX + 1];
__device__ int    g_cnt[VMAX];
__device__ int2   g_edge[EMAX];               // (col, val bits) interleaved
__device__ __half g_xn [(size_t)VMAX * 128];  // BN'ed input (v,b,c) fp16 (layer0 X0)
__device__ float  g_xnf[(size_t)VMAX * 128];  // BN'ed input fp32 (residual path)
__device__ __half g_x0[(size_t)VMAX * 256];
__device__ __half g_x1[(size_t)VMAX * 256];
__device__ __half g_x2[(size_t)VMAX * 256];
__device__ __half g_x3[(size_t)VMAX * 256];
__device__ __half g_t [(size_t)VMAX * 256];   // fp16 einsum out (layers 0,1), (v,b,c)
__device__ float  g_of[(size_t)VMAX * 128];   // fp32 einsum out (layer 2), (v,b,o)
__device__ float  g_stats[128];               // [0:64) sum, [64:128) sumsq
__device__ __half g_w0[4 * 64 * 32];          // layer0 W^T (k,o,c) fp16
__device__ __half g_w1[4 * 64 * 64];          // layer1
__device__ __half g_w2[4 * 32 * 64];          // layer2

// =============== fused kernel 1: edge histogram + BN(32) stats ===============
// blocks [0, nbe): histogram; blocks [nbe, nbe+1024): input stats (128 slabs x 8)
__global__ void __launch_bounds__(256) k_hist_stats(const int* __restrict__ rows, int E,
                                                    const float* __restrict__ x, int V,
                                                    int nbe) {
    if (blockIdx.x < (unsigned)nbe) {
        int e = blockIdx.x * 256 + threadIdx.x;
        if (e < E) atomicAdd(&g_cnt[rows[e]], 1);
        return;
    }
    int j = blockIdx.x - nbe;        // 0..1023
    int slab = j >> 3;               // 0..127
    int c = slab & 31;
    const float* p = x + (size_t)slab * V;
    __shared__ float ss[256], sq[256];
    float s = 0.f, q = 0.f;
    for (int i = (j & 7) * 256 + threadIdx.x; i < V; i += 8 * 256) {
        float t = p[i];
        s += t; q += t * t;
    }
    int tid = threadIdx.x;
    ss[tid] = s; sq[tid] = q;
    __syncthreads();
    for (int o = 128; o > 0; o >>= 1) {
        if (tid < o) { ss[tid] += ss[tid + o]; sq[tid] += sq[tid + o]; }
        __syncthreads();
    }
    if (tid == 0) { atomicAdd(&g_stats[c], ss[0]); atomicAdd(&g_stats[64 + c], sq[0]); }
}

// =============== fused kernel 2: CSR scan (block 0) + weight convert =========
__global__ void __launch_bounds__(1024) k_scan_wconv(int V,
                                                     const float* __restrict__ w0,
                                                     const float* __restrict__ w1,
                                                     const float* __restrict__ w2) {
    if (blockIdx.x == 0) {
        __shared__ int sh[1024];
        __shared__ int s_carry;
        int tid = threadIdx.x;
        if (tid == 0) s_carry = 0;
        __syncthreads();
        for (int base = 0; base < V; base += 1024) {
            int i = base + tid;
            int v = 0;
            if (i < V) { v = g_cnt[i]; g_cnt[i] = 0; }
            sh[tid] = v;
            __syncthreads();
            for (int off = 1; off < 1024; off <<= 1) {
                int t = (tid >= off) ? sh[tid - off] : 0;
                __syncthreads();
                sh[tid] += t;
                __syncthreads();
            }
            int carry = s_carry;
            if (i < V) g_rowptr[i] = carry + sh[tid] - v;
            __syncthreads();
            if (tid == 1023) s_carry = carry + sh[1023];
            __syncthreads();
        }
        if (threadIdx.x == 0) g_rowptr[V] = s_carry;
        return;
    }
    int i0 = (blockIdx.x - 1) * 1024 + threadIdx.x;
    int stride = (gridDim.x - 1) * 1024;
    for (int i = i0; i < 4 * 32 * 64; i += stride) {   // layer0: CIN=32, COUT=64
        int k = i / (32 * 64), r = i % (32 * 64);
        int o = r / 32, c = r % 32;
        g_w0[i] = __float2half_rn(w0[(k * 32 + c) * 64 + o]);
    }
    for (int i = i0; i < 4 * 64 * 64; i += stride) {   // layer1
        int k = i / (64 * 64), r = i % (64 * 64);
        int o = r / 64, c = r % 64;
        g_w1[i] = __float2half_rn(w1[(k * 64 + c) * 64 + o]);
    }
    for (int i = i0; i < 4 * 32 * 64; i += stride) {   // layer2: CIN=64, COUT=32
        int k = i / (32 * 64), r = i % (32 * 64);
        int o = r / 64, c = r % 64;
        g_w2[i] = __float2half_rn(w2[(k * 64 + c) * 32 + o]);
    }
}

// =============== fused kernel 3: CSR fill + BN(32) apply/transpose ===========
// blocks [0, nbe): fill edges; blocks [nbe, nbe+NB32): apply (32 vertices each)
__global__ void __launch_bounds__(256) k_fill_apply(const int* __restrict__ rows,
                                                    const int* __restrict__ cols,
                                                    const float* __restrict__ vals, int E,
                                                    const float* __restrict__ x,
                                                    const float* __restrict__ gamma,
                                                    const float* __restrict__ beta,
                                                    float invN, int V, int nbe) {
    if (blockIdx.x < (unsigned)nbe) {
        int e = blockIdx.x * 256 + threadIdx.x;
        if (e >= E) return;
        int r = rows[e];
        int pos = g_rowptr[r] + atomicAdd(&g_cnt[r], 1);
        g_edge[pos] = make_int2(cols[e], __float_as_int(vals[e]));
        return;
    }
    __shared__ float sh[32 * 129];
    __shared__ float ssc[32], ssh[32];
    if (threadIdx.x < 32) {
        int c = threadIdx.x;
        float m = g_stats[c] * invN;
        float var = g_stats[64 + c] * invN - m * m;
        float inv = rsqrtf(var + 1e-5f);
        float sc = gamma[c] * inv;
        ssc[c] = sc;
        ssh[c] = beta[c] - sc * m;
    }
    __syncthreads();
    int v0 = (blockIdx.x - nbe) * 32;
    for (int j = threadIdx.x; j < 4096; j += 256) {
        int f = j >> 5;          // slab = b*32+c
        int vl = j & 31;
        int c = f & 31;
        int v = v0 + vl;
        float t = 0.f;
        if (v < V) t = x[(size_t)f * V + v];
        sh[vl * 129 + f] = ssc[c] * t + ssh[c];
    }
    __syncthreads();
    for (int j = threadIdx.x; j < 4096; j += 256) {
        int vl = j >> 7;
        int f = j & 127;
        int v = v0 + vl;
        if (v < V) {
            float t = sh[vl * 129 + f];
            size_t idx = (size_t)v * 128 + f;
            g_xn[idx] = __float2half_rn(t);
            g_xnf[idx] = t;
        }
    }
}

// ---------------- BN stats on fp16 (v,b,c64) ----------------
__global__ void __launch_bounds__(128) k_stats_vm(const __half2* __restrict__ T, int V) {
    __shared__ float bs[64], bq[64];
    int t = threadIdx.x;
    if (t < 64) { bs[t] = 0.f; bq[t] = 0.f; }
    __syncthreads();
    float s0 = 0.f, q0 = 0.f, s1 = 0.f, q1 = 0.f;
    for (int v = blockIdx.x; v < V; v += gridDim.x) {
        float2 f = __half22float2(T[(size_t)v * 128 + t]);
        s0 += f.x; q0 += f.x * f.x;
        s1 += f.y; q1 += f.y * f.y;
    }
    int c0 = (2 * t) & 63;
    atomicAdd(&bs[c0], s0);     atomicAdd(&bq[c0], q0);
    atomicAdd(&bs[c0 + 1], s1); atomicAdd(&bq[c0 + 1], q1);
    __syncthreads();
    if (t < 64) {
        atomicAdd(&g_stats[t], bs[t]);
        atomicAdd(&g_stats[64 + t], bq[t]);
    }
}

// normalize fp16 (v,b,c64)
__global__ void __launch_bounds__(256) k_apply_vm(uint2* __restrict__ dst,
                                                  const uint2* __restrict__ src,
                                                  const float* __restrict__ gamma,
                                                  const float* __restrict__ beta,
                                                  float invN, int n) {
    __shared__ float ssc[64], ssh[64];
    if (threadIdx.x < 64) {
        int c = threadIdx.x;
        float m = g_stats[c] * invN;
        float var = g_stats[64 + c] * invN - m * m;
        float inv = rsqrtf(var + 1e-5f);
        float sc = gamma[c] * inv;
        ssc[c] = sc;
        ssh[c] = beta[c] - sc * m;
    }
    __syncthreads();
    int i = blockIdx.x * blockDim.x + threadIdx.x;
    if (i >= n) return;
    int c0 = (i & 15) * 4;
    float4 s4 = *(float4*)&ssc[c0];
    float4 h4 = *(float4*)&ssh[c0];
    uint2 raw = src[i];
    float2 fa = __half22float2(*(__half2*)&raw.x);
    float2 fb = __half22float2(*(__half2*)&raw.y);
    fa.x = fa.x * s4.x + h4.x; fa.y = fa.y * s4.y + h4.y;
    fb.x = fb.x * s4.z + h4.z; fb.y = fb.y * s4.w + h4.w;
    uint2 o;
    *(__half2*)&o.x = __floats2half2_rn(fa.x, fa.y);
    *(__half2*)&o.y = __floats2half2_rn(fb.x, fb.y);
    dst[i] = o;
}

// ---------------- SpMM fp16: y = alpha*L*x + beta*z ----------------
template <int HPL>
__device__ __forceinline__ void gacc(float* acc, const __half* p, float w) {
    if constexpr (HPL == 8) {
        uint4 raw = *(const uint4*)p;
        float2 f;
        f = __half22float2(*(__half2*)&raw.x); acc[0] += w * f.x; acc[1] += w * f.y;
        f = __half22float2(*(__half2*)&raw.y); acc[2] += w * f.x; acc[3] += w * f.y;
        f = __half22float2(*(__half2*)&raw.z); acc[4] += w * f.x; acc[5] += w * f.y;
        f = __half22float2(*(__half2*)&raw.w); acc[6] += w * f.x; acc[7] += w * f.y;
    } else {
        uint2 raw = *(const uint2*)p;
        float2 f;
        f = __half22float2(*(__half2*)&raw.x); acc[0] += w * f.x; acc[1] += w * f.y;
        f = __half22float2(*(__half2*)&raw.y); acc[2] += w * f.x; acc[3] += w * f.y;
    }
}

template <int F>
__global__ void __launch_bounds__(256) k_spmm_h(__half* __restrict__ y,
                                                const __half* __restrict__ x,
                                                const __half* __restrict__ z,
                                                float alpha, float beta, int V) {
    constexpr int HPL = F / 32;   // 4 or 8
    int row = (blockIdx.x * 256 + threadIdx.x) >> 5;
    if (row >= V) return;
    int lane = threadIdx.x & 31;
    const __half* xb = x + lane * HPL;
    int beg = g_rowptr[row], end = g_rowptr[row + 1];
    float acc[HPL];
#pragma unroll
    for (int i = 0; i < HPL; i++) acc[i] = 0.f;

    int e = beg;
    int n8 = beg + ((end - beg) & ~7);
    for (; e < n8; e += 8) {
        int2 ed[8];
#pragma unroll
        for (int j = 0; j < 8; j++) ed[j] = g_edge[e + j];
        if constexpr (HPL == 8) {
            uint4 raw[8];
#pragma unroll
            for (int j = 0; j < 8; j++)
                raw[j] = *(const uint4*)(xb + (size_t)ed[j].x * F);
#pragma unroll
            for (int j = 0; j < 8; j++) {
                float w = __int_as_float(ed[j].y);
                float2 f;
                f = __half22float2(*(__half2*)&raw[j].x); acc[0] += w * f.x; acc[1] += w * f.y;
                f = __half22float2(*(__half2*)&raw[j].y); acc[2] += w * f.x; acc[3] += w * f.y;
                f = __half22float2(*(__half2*)&raw[j].z); acc[4] += w * f.x; acc[5] += w * f.y;
                f = __half22float2(*(__half2*)&raw[j].w); acc[6] += w * f.x; acc[7] += w * f.y;
            }
        } else {
            uint2 raw[8];
#pragma unroll
            for (int j = 0; j < 8; j++)
                raw[j] = *(const uint2*)(xb + (size_t)ed[j].x * F);
#pragma unroll
            for (int j = 0; j < 8; j++) {
                float w = __int_as_float(ed[j].y);
                float2 f;
                f = __half22float2(*(__half2*)&raw[j].x); acc[0] += w * f.x; acc[1] += w * f.y;
                f = __half22float2(*(__half2*)&raw[j].y); acc[2] += w * f.x; acc[3] += w * f.y;
            }
        }
    }
    for (; e < end; e++) {
        int2 ed = g_edge[e];
        gacc<HPL>(acc, xb + (size_t)ed.x * F, __int_as_float(ed.y));
    }

    size_t oi = (size_t)row * F + lane * HPL;
    if (beta != 0.f) {
#pragma unroll
        for (int i = 0; i < HPL; i += 2) {
            float2 f = __half22float2(*(const __half2*)(z + oi + i));
            acc[i]     = alpha * acc[i]     + beta * f.x;
            acc[i + 1] = alpha * acc[i + 1] + beta * f.y;
        }
    } else if (alpha != 1.f) {
#pragma unroll
        for (int i = 0; i < HPL; i++) acc[i] *= alpha;
    }
    if constexpr (HPL == 8) {
        uint4 o;
        *(__half2*)&o.x = __floats2half2_rn(acc[0], acc[1]);
        *(__half2*)&o.y = __floats2half2_rn(acc[2], acc[3]);
        *(__half2*)&o.z = __floats2half2_rn(acc[4], acc[5]);
        *(__half2*)&o.w = __floats2half2_rn(acc[6], acc[7]);
        *(uint4*)(y + oi) = o;
    } else {
        uint2 o;
        *(__half2*)&o.x = __floats2half2_rn(acc[0], acc[1]);
        *(__half2*)&o.y = __floats2half2_rn(acc[2], acc[3]);
        *(uint2*)(y + oi) = o;
    }
}

// ---------------- tensor-core einsum ----------------------------------------------
template <int CIN, int COUT, bool RELU, typename OT>
__global__ void __launch_bounds__(128) k_einmma(OT* __restrict__ out,
                                                const __half* __restrict__ X0,
                                                const __half* __restrict__ X1,
                                                const __half* __restrict__ X2,
                                                const __half* __restrict__ X3,
                                                const __half* __restrict__ Wt,
                                                const float* __restrict__ bias,
                                                int rows4) {
    constexpr int CHUNKS = 4 * CIN / 16;
    constexpr int NT = COUT / 8;
    constexpr int WROW = CIN + 2;
    __shared__ __half sW[4 * COUT * WROW];
    __shared__ float  sb[COUT];
    __shared__ __half sA[4][16 * 24];

    for (int i = threadIdx.x; i < 4 * COUT * CIN / 2; i += 128) {
        int row = (2 * i) / CIN;
        int c = (2 * i) % CIN;
        *(__half2*)&sW[row * WROW + c] = *(const __half2*)&Wt[2 * i];
    }
    for (int i = threadIdx.x; i < COUT; i += 128) sb[i] = bias[i];
    __syncthreads();

    int warp = threadIdx.x >> 5;
    int lane = threadIdx.x & 31;
    int mbase = blockIdx.x * 64 + warp * 16;

    const __half* Xs[4] = {X0, X1, X2, X3};

    float acc[NT][4];
#pragma unroll
    for (int n = 0; n < NT; n++)
#pragma unroll
        for (int j = 0; j < 4; j++) acc[n][j] = 0.f;

    uint32_t sa_base;
    {
        const void* p = &sA[warp][0];
        asm("{ .reg .u64 t; cvta.to.shared.u64 t, %1; cvt.u32.u64 %0, t; }"
            : "=r"(sa_base) : "l"(p));
    }
    int ldrow = lane & 15;
    int ldhi = lane >> 4;
    uint32_t lm_addr = sa_base + (ldrow * 24 + ldhi * 8) * 2;

    int srow = lane >> 1;
    int soff = (lane & 1) * 8;
    int gr = mbase + srow;
    bool grok = (gr < rows4);

    int g = lane >> 2;
    int t2 = (lane & 3) * 2;

#pragma unroll
    for (int ch = 0; ch < CHUNKS; ch++) {
        const int kbuf = ch / (CIN / 16);
        const int c0 = (ch % (CIN / 16)) * 16;
        uint4 av = make_uint4(0, 0, 0, 0);
        if (grok) av = *(const uint4*)(Xs[kbuf] + (size_t)gr * CIN + c0 + soff);
        __syncwarp();
        *(uint4*)&sA[warp][srow * 24 + soff] = av;
        __syncwarp();
        uint32_t a0, a1, a2, a3;
        asm volatile("ldmatrix.sync.aligned.m8n8.x4.shared.b16 {%0,%1,%2,%3}, [%4];"
                     : "=r"(a0), "=r"(a1), "=r"(a2), "=r"(a3) : "r"(lm_addr));
#pragma unroll
        for (int nt = 0; nt < NT; nt++) {
            int o = nt * 8 + g;
            const __half* wrow = &sW[(kbuf * COUT + o) * WROW + c0 + t2];
            uint32_t b0 = *(const uint32_t*)wrow;
            uint32_t b1 = *(const uint32_t*)(wrow + 8);
            asm volatile(
                "mma.sync.aligned.m16n8k16.row.col.f32.f16.f16.f32 "
                "{%0,%1,%2,%3}, {%4,%5,%6,%7}, {%8,%9}, {%0,%1,%2,%3};"
                : "+f"(acc[nt][0]), "+f"(acc[nt][1]), "+f"(acc[nt][2]), "+f"(acc[nt][3])
                : "r"(a0), "r"(a1), "r"(a2), "r"(a3), "r"(b0), "r"(b1));
        }
    }

    int r0 = mbase + g;
    int r1 = r0 + 8;
#pragma unroll
    for (int nt = 0; nt < NT; nt++) {
        int o0 = nt * 8 + t2;
        float bb0 = sb[o0], bb1 = sb[o0 + 1];
        float v00 = acc[nt][0] + bb0, v01 = acc[nt][1] + bb1;
        float v10 = acc[nt][2] + bb0, v11 = acc[nt][3] + bb1;
        if (RELU) {
            v00 = fmaxf(v00, 0.f); v01 = fmaxf(v01, 0.f);
            v10 = fmaxf(v10, 0.f); v11 = fmaxf(v11, 0.f);
        }
        if constexpr (sizeof(OT) == 2) {
            if (r0 < rows4)
                *(__half2*)((__half*)out + (size_t)r0 * COUT + o0) = __floats2half2_rn(v00, v01);
            if (r1 < rows4)
                *(__half2*)((__half*)out + (size_t)r1 * COUT + o0) = __floats2half2_rn(v10, v11);
        } else {
            if (r0 < rows4)
                *(float2*)((float*)out + (size_t)r0 * COUT + o0) = make_float2(v00, v01);
            if (r1 < rows4)
                *(float2*)((float*)out + (size_t)r1 * COUT + o0) = make_float2(v10, v11);
        }
    }
}

// ---------------- final residual + relu + transpose to fp32 (B,32,V) ----------------
__global__ void __launch_bounds__(128) k_final(float* __restrict__ out,
                                               const float* __restrict__ R, int V) {
    __shared__ float sh[32 * 129];
    int v0 = blockIdx.x * 32;
    for (int j = threadIdx.x; j < 4096; j += 128) {
        int vl = j >> 7;
        int f = j & 127;
        int v = v0 + vl;
        float t = 0.f;
        if (v < V) {
            size_t idx = (size_t)v * 128 + f;
            t = fmaxf(R[idx] + g_xnf[idx], 0.f);
        }
        sh[vl * 129 + f] = t;
    }
    __syncthreads();
    for (int j = threadIdx.x; j < 4096; j += 128) {
        int f = j >> 5;
        int vl = j & 31;
        int v = v0 + vl;
        if (v < V) out[(size_t)f * V + v] = sh[vl * 129 + f];
    }
}

// ---------------- host orchestration ----------------
extern "C" void kernel_launch(void* const* d_in, const int* in_sizes, int n_in,
                              void* d_out, int out_size) {
    const float* x        = (const float*)d_in[0];
    const int*   ei       = (const int*)d_in[1];
    const float* lap_vals = (const float*)d_in[2];
    const float* in_bn_g  = (const float*)d_in[3];
    const float* in_bn_b  = (const float*)d_in[4];
    const float* in_w     = (const float*)d_in[5];
    const float* in_b     = (const float*)d_in[6];
    const float* h0_bn_g  = (const float*)d_in[7];
    const float* h0_bn_b  = (const float*)d_in[8];
    const float* h0_w     = (const float*)d_in[9];
    const float* h0_b     = (const float*)d_in[10];
    const float* h1_bn_g  = (const float*)d_in[11];
    const float* h1_bn_b  = (const float*)d_in[12];
    const float* h1_w     = (const float*)d_in[13];
    const float* h1_b     = (const float*)d_in[14];

    const int V = in_sizes[0] / 128;
    const int E = in_sizes[1] / 2;
    const int rows4 = 4 * V;
    const int* rows = ei;
    const int* cols = ei + E;
    const float invN = 1.0f / (4.0f * (float)V);

    __half *xn, *x0, *x1, *x2, *x3, *tb, *w0, *w1, *w2;
    float *of;
    void *cntp, *statp;
    cudaGetSymbolAddress((void**)&xn, g_xn);
    cudaGetSymbolAddress((void**)&x0, g_x0);
    cudaGetSymbolAddress((void**)&x1, g_x1);
    cudaGetSymbolAddress((void**)&x2, g_x2);
    cudaGetSymbolAddress((void**)&x3, g_x3);
    cudaGetSymbolAddress((void**)&tb, g_t);
    cudaGetSymbolAddress((void**)&of, g_of);
    cudaGetSymbolAddress((void**)&w0, g_w0);
    cudaGetSymbolAddress((void**)&w1, g_w1);
    cudaGetSymbolAddress((void**)&w2, g_w2);
    cudaGetSymbolAddress(&cntp, g_cnt);
    cudaGetSymbolAddress(&statp, g_stats);

    const int NBE  = (E + 255) / 256;
    const int NB32 = (V + 31) / 32;
    const int NBW  = (V + 7) / 8;            // spmm: one warp per row
    const int NEM  = (rows4 + 63) / 64;      // einmma M-blocks
    const int NAPP = (V * 64 + 255) / 256;

    // ---- fused prologue: CSR build + BN(32) stats/apply + weight convert ----
    cudaMemsetAsync(cntp, 0, (size_t)V * 4);
    cudaMemsetAsync(statp, 0, 128 * 4);
    k_hist_stats<<<NBE + 1024, 256>>>(rows, E, x, V, NBE);               // kernel #1
    k_scan_wconv<<<33, 1024>>>(V, in_w, h0_w, h1_w);                     // kernel #2
    k_fill_apply<<<NBE + NB32, 256>>>(rows, cols, lap_vals, E,
                                      x, in_bn_g, in_bn_b, invN, V, NBE);// kernel #3

    // ---- layer 0: Cheb 32->64 ----
    k_spmm_h<128><<<NBW, 256>>>(x1, xn, nullptr, 1.f, 0.f, V);           // kernel #4 (profiled)
    k_spmm_h<128><<<NBW, 256>>>(x2, x1, xn, 2.f, -1.f, V);
    k_spmm_h<128><<<NBW, 256>>>(x3, x2, x1, 2.f, -1.f, V);
    k_einmma<32, 64, true, __half><<<NEM, 128>>>(tb, xn, x1, x2, x3, w0, in_b, rows4);

    // ---- layer 1: BN(64) + Cheb 64->64 ----
    cudaMemsetAsync(statp, 0, 128 * 4);
    k_stats_vm<<<1024, 128>>>((const __half2*)tb, V);
    k_apply_vm<<<NAPP, 256>>>((uint2*)x0, (const uint2*)tb, h0_bn_g, h0_bn_b, invN, V * 64);

    k_spmm_h<256><<<NBW, 256>>>(x1, x0, nullptr, 1.f, 0.f, V);
    k_spmm_h<256><<<NBW, 256>>>(x2, x1, x0, 2.f, -1.f, V);
    k_spmm_h<256><<<NBW, 256>>>(x3, x2, x1, 2.f, -1.f, V);
    k_einmma<64, 64, true, __half><<<NEM, 128>>>(tb, x0, x1, x2, x3, w1, h0_b, rows4);

    // ---- layer 2: BN(64) + Cheb 64->32, fp32 out, no relu ----
    cudaMemsetAsync(statp, 0, 128 * 4);
    k_stats_vm<<<1024, 128>>>((const __half2*)tb, V);
    k_apply_vm<<<NAPP, 256>>>((uint2*)x0, (const uint2*)tb, h1_bn_g, h1_bn_b, invN, V * 64);

    k_spmm_h<256><<<NBW, 256>>>(x1, x0, nullptr, 1.f, 0.f, V);
    k_spmm_h<256><<<NBW, 256>>>(x2, x1, x0, 2.f, -1.f, V);
    k_spmm_h<256><<<NBW, 256>>>(x3, x2, x1, 2.f, -1.f, V);
    k_einmma<64, 32, false, float><<<NEM, 128>>>(of, x0, x1, x2, x3, w2, h1_b, rows4);

    // ---- residual + relu + transpose to (B,32,V) fp32 ----
    k_final<<<NB32, 128>>>((float*)d_out, of, V);
    (void)n_in; (void)out_size;
}